// round 1
// baseline (speedup 1.0000x reference)
#include <cuda_runtime.h>

#define B_    128
#define IN_   1024
#define OUT_  1024

__device__ __constant__ float c_dummy; // keep nvcc happy about empty const use

constexpr float BETA    = 0.99f;
constexpr float THRESH  = 1.0f;
constexpr float RESETV  = 0.8f;
constexpr float INV_TAU = 1.0f / 20.0f;
constexpr float A_SC    = 0.005f / 128.0f;   // A_POS(=A_NEG) / B

// Packed per-(batch,index) tables:
//   Ipack[b,i] = (dp, e^{+dp/20}, e^{-dp/20}, 0)
//   Opack[b,o] = (df, e^{-df/20}, e^{+df/20}, 0)
__device__ float4 g_Ipack[B_ * IN_];
__device__ float4 g_Opack[B_ * OUT_];

// ---------------------------------------------------------------------------
// Kernel 1: weighted = spikes @ W^T, LIF update, spike/mem outputs, Opack.
// grid (8, 16): x = o-chunk of 128, y = b-chunk of 8. 128 threads.
// ---------------------------------------------------------------------------
__global__ __launch_bounds__(128) void k_matmul_lif(
    const float* __restrict__ spikes,
    const float* __restrict__ W,
    const float* __restrict__ membrane,
    const float* __restrict__ dfire,
    float* __restrict__ out_spike,
    float* __restrict__ out_mem)
{
    __shared__ float s[8][IN_];               // 32 KB: 8 batch rows of spikes

    const int tid = threadIdx.x;
    const int bb0 = blockIdx.y * 8;

    // cooperative load of 8 spike rows (float4-coalesced)
    const float4* sp4 = reinterpret_cast<const float4*>(spikes);
    float4* s4 = reinterpret_cast<float4*>(&s[0][0]);
    #pragma unroll
    for (int t = tid; t < 8 * IN_ / 4; t += 128) {
        int b = t / (IN_ / 4);
        int k = t % (IN_ / 4);
        s4[t] = sp4[(bb0 + b) * (IN_ / 4) + k];
    }
    __syncthreads();

    const int o = blockIdx.x * 128 + tid;
    float acc[8];
    #pragma unroll
    for (int b = 0; b < 8; b++) acc[b] = 0.0f;

    const float4* W4 = reinterpret_cast<const float4*>(W + (size_t)o * IN_);
    #pragma unroll 4
    for (int kc = 0; kc < IN_ / 4; kc++) {
        float4 w = W4[kc];
        #pragma unroll
        for (int b = 0; b < 8; b++) {
            float4 sv = reinterpret_cast<float4*>(s[b])[kc];  // broadcast
            acc[b] += w.x * sv.x + w.y * sv.y + w.z * sv.z + w.w * sv.w;
        }
    }

    #pragma unroll
    for (int b = 0; b < 8; b++) {
        int gb  = bb0 + b;
        int idx = gb * OUT_ + o;
        float mem = membrane[idx] * BETA + acc[b];
        float sp  = (mem > THRESH) ? 1.0f : 0.0f;
        if (sp > 0.0f) mem -= RESETV;
        out_spike[idx] = sp;
        out_mem[idx]   = mem;
        float df = (sp > 0.0f) ? 0.0f : dfire[idx] + 1.0f;
        g_Opack[idx] = make_float4(df, __expf(-df * INV_TAU), __expf(df * INV_TAU), 0.0f);
    }
}

// ---------------------------------------------------------------------------
// Kernel 2: build Ipack from input spikes / delta_pre.
// ---------------------------------------------------------------------------
__global__ __launch_bounds__(256) void k_ipack(
    const float* __restrict__ spikes,
    const float* __restrict__ dpre)
{
    int idx = blockIdx.x * 256 + threadIdx.x;
    if (idx < B_ * IN_) {
        float dp = (spikes[idx] > 0.0f) ? 0.0f : dpre[idx] + 1.0f;
        g_Ipack[idx] = make_float4(dp, __expf(dp * INV_TAU), __expf(-dp * INV_TAU), 0.0f);
    }
}

// ---------------------------------------------------------------------------
// Kernel 3: pairwise STDP accumulation over batches + W update.
// Block tile: 64 (i) x 64 (o). 256 threads as 16x16, 4x4 register tile each.
// Per element: wc = (df>dp)? p*r : (df<dp)? -q*s : 0   (strict compares
// reproduce the reference's exact-zero at df==dp).
// ---------------------------------------------------------------------------
__global__ __launch_bounds__(256) void k_stdp(
    const float* __restrict__ W,
    float* __restrict__ outW)
{
    __shared__ float4 sI[8][64];   // 8 KB
    __shared__ float4 sO[8][64];   // 8 KB

    const int tid = threadIdx.x;
    const int tx  = tid & 15;      // o sub-tile
    const int ty  = tid >> 4;      // i sub-tile
    const int oBase = blockIdx.x * 64;
    const int iBase = blockIdx.y * 64;

    float acc[4][4];
    #pragma unroll
    for (int a = 0; a < 4; a++)
        #pragma unroll
        for (int c = 0; c < 4; c++) acc[a][c] = 0.0f;

    for (int cb = 0; cb < B_ / 8; cb++) {
        // cooperative staging: 512 float4 per array, coalesced
        #pragma unroll
        for (int t = tid; t < 512; t += 256) {
            int b = t >> 6, idx = t & 63;
            sI[b][idx] = g_Ipack[(cb * 8 + b) * IN_  + iBase + idx];
            sO[b][idx] = g_Opack[(cb * 8 + b) * OUT_ + oBase + idx];
        }
        __syncthreads();

        #pragma unroll
        for (int b = 0; b < 8; b++) {
            float4 iv[4], ov[4];
            #pragma unroll
            for (int j = 0; j < 4; j++) {
                iv[j] = sI[b][ty * 4 + j];
                ov[j] = sO[b][tx * 4 + j];
            }
            #pragma unroll
            for (int a = 0; a < 4; a++) {
                #pragma unroll
                for (int c = 0; c < 4; c++) {
                    float pr = iv[a].y * ov[c].y;   // e^{(dp-df)/20}
                    float qs = iv[a].z * ov[c].z;   // e^{(df-dp)/20}
                    if (ov[c].x > iv[a].x)      acc[a][c] += pr;
                    else if (ov[c].x < iv[a].x) acc[a][c] -= qs;
                }
            }
        }
        __syncthreads();
    }

    // epilogue: new_W[o, i0..i0+3] as float4
    const int i0 = iBase + ty * 4;
    #pragma unroll
    for (int c = 0; c < 4; c++) {
        int o = oBase + tx * 4 + c;
        const float4 w = *reinterpret_cast<const float4*>(W + (size_t)o * IN_ + i0);
        float4 v = make_float4(w.x + acc[0][c] * A_SC,
                               w.y + acc[1][c] * A_SC,
                               w.z + acc[2][c] * A_SC,
                               w.w + acc[3][c] * A_SC);
        *reinterpret_cast<float4*>(outW + (size_t)o * IN_ + i0) = v;
    }
}

// ---------------------------------------------------------------------------
extern "C" void kernel_launch(void* const* d_in, const int* in_sizes, int n_in,
                              void* d_out, int out_size)
{
    const float* spikes   = (const float*)d_in[0];
    const float* W        = (const float*)d_in[1];
    const float* membrane = (const float*)d_in[2];
    const float* dpre     = (const float*)d_in[3];
    const float* dfire    = (const float*)d_in[4];

    float* out       = (float*)d_out;
    float* out_spike = out;                                // (B, OUT)
    float* out_W     = out + B_ * OUT_;                    // (OUT, IN)
    float* out_mem   = out + B_ * OUT_ + (size_t)OUT_ * IN_; // (B, OUT)

    k_matmul_lif<<<dim3(8, 16), 128>>>(spikes, W, membrane, dfire, out_spike, out_mem);
    k_ipack<<<(B_ * IN_ + 255) / 256, 256>>>(spikes, dpre);
    k_stdp<<<dim3(16, 16), 256>>>(W, out_W);
}

// round 2
// speedup vs baseline: 2.2038x; 2.2038x over previous
#include <cuda_runtime.h>
#include <cuda_fp16.h>

#define B_    128
#define IN_   1024
#define OUT_  1024

constexpr float BETA    = 0.99f;
constexpr float THRESH  = 1.0f;
constexpr float RESETV  = 0.8f;
constexpr float INV_TAU = 0.05f;              // 1/20
constexpr float A_SC    = 0.005f / 128.0f;    // A / B

// ---- device scratch (static, allocation-free) ------------------------------
__device__ float g_Wt[IN_ * OUT_];            // Wt[k][o] = W[o][k]
__device__ float g_part[4 * B_ * OUT_];       // k-split matmul partials
__device__ uint4 g_Ipk[B_ * IN_];             // (dp2, p2, q2, pad) broadcast half2
__device__ uint4 g_Opk[B_ * OUT_ / 2];        // per o-pair (df2, r2, -s2, pad)

__device__ __forceinline__ __half2 u2h(unsigned u) { return *reinterpret_cast<__half2*>(&u); }
__device__ __forceinline__ unsigned h2u(__half2 h) { return *reinterpret_cast<unsigned*>(&h); }

// ---------------------------------------------------------------------------
// Transpose W (OUT,IN) -> Wt (IN,OUT), 32x32 tiles.
// ---------------------------------------------------------------------------
__global__ __launch_bounds__(256) void k_transpose(const float* __restrict__ W)
{
    __shared__ float t[32][33];
    const int bx = blockIdx.x * 32;   // k range
    const int by = blockIdx.y * 32;   // o range
    const int tx = threadIdx.x, ty = threadIdx.y;  // (32, 8)
    #pragma unroll
    for (int i = 0; i < 32; i += 8)
        t[ty + i][tx] = W[(size_t)(by + ty + i) * IN_ + bx + tx];
    __syncthreads();
    #pragma unroll
    for (int i = 0; i < 32; i += 8)
        g_Wt[(size_t)(bx + ty + i) * OUT_ + by + tx] = t[tx][ty + i];
}

// ---------------------------------------------------------------------------
// Ipack: per (b,i) -> (dp, e^{dp/20}, e^{-dp/20}) broadcast into half2 lanes.
// ---------------------------------------------------------------------------
__global__ __launch_bounds__(256) void k_ipack(
    const float* __restrict__ spikes, const float* __restrict__ dpre)
{
    int idx = blockIdx.x * 256 + threadIdx.x;  // B_*IN_ threads
    float dp = (spikes[idx] > 0.0f) ? 0.0f : dpre[idx] + 1.0f;
    __half2 d2 = __float2half2_rn(dp);
    __half2 p2 = __float2half2_rn(__expf(dp * INV_TAU));
    __half2 q2 = __float2half2_rn(__expf(-dp * INV_TAU));
    uint4 u;
    u.x = h2u(d2); u.y = h2u(p2); u.z = h2u(q2); u.w = 0;
    g_Ipk[idx] = u;
}

// ---------------------------------------------------------------------------
// Matmul partials: weighted_part[kq][b][o] = sum_{k in quarter} s[b,k]*Wt[k,o].
// grid (32 b-blocks of 4, 4 k-quarters), 256 threads: thread owns 4 o (float4).
// Wt reads are lane-coalesced; spike values broadcast from shared.
// ---------------------------------------------------------------------------
__global__ __launch_bounds__(256) void k_matmul(const float* __restrict__ spikes)
{
    __shared__ float s[4][256];
    const int tid = threadIdx.x;
    const int bb0 = blockIdx.x * 4;
    const int kq  = blockIdx.y;

    // stage 4 spike rows (k-quarter slice), float4-coalesced
    {
        const float4* sp4 = reinterpret_cast<const float4*>(spikes);
        int b = tid >> 6, kf = tid & 63;
        reinterpret_cast<float4*>(s)[tid] = sp4[(bb0 + b) * (IN_ / 4) + kq * 64 + kf];
    }
    __syncthreads();

    float4 acc[4];
    #pragma unroll
    for (int b = 0; b < 4; b++) acc[b] = make_float4(0.f, 0.f, 0.f, 0.f);

    const float4* Wt4 = reinterpret_cast<const float4*>(g_Wt);
    #pragma unroll 4
    for (int k = 0; k < 256; k++) {
        float4 w = Wt4[(size_t)(kq * 256 + k) * (OUT_ / 4) + tid];
        #pragma unroll
        for (int b = 0; b < 4; b++) {
            float sv = s[b][k];      // broadcast
            acc[b].x += w.x * sv; acc[b].y += w.y * sv;
            acc[b].z += w.z * sv; acc[b].w += w.w * sv;
        }
    }
    #pragma unroll
    for (int b = 0; b < 4; b++)
        reinterpret_cast<float4*>(g_part)[((kq * B_ + bb0 + b) * OUT_) / 4 + tid] = acc[b];
}

// ---------------------------------------------------------------------------
// LIF: reduce 4 partials, threshold/reset, write spike+mem, build Opack pairs.
// One thread per o-pair.
// ---------------------------------------------------------------------------
__global__ __launch_bounds__(256) void k_lif(
    const float* __restrict__ membrane, const float* __restrict__ dfire,
    float* __restrict__ out_spike, float* __restrict__ out_mem)
{
    int idx = blockIdx.x * 256 + threadIdx.x;     // B_*OUT_/2
    int b = idx >> 9, opi = idx & 511;
    int base = b * OUT_ + opi * 2;

    float w0 = 0.f, w1 = 0.f;
    #pragma unroll
    for (int kq = 0; kq < 4; kq++) {
        float2 p = *reinterpret_cast<const float2*>(&g_part[(kq * B_ + b) * OUT_ + opi * 2]);
        w0 += p.x; w1 += p.y;
    }
    float2 mem = *reinterpret_cast<const float2*>(&membrane[base]);
    float2 dfr = *reinterpret_cast<const float2*>(&dfire[base]);

    float m0 = mem.x * BETA + w0, m1 = mem.y * BETA + w1;
    float s0 = (m0 > THRESH) ? 1.0f : 0.0f;
    float s1 = (m1 > THRESH) ? 1.0f : 0.0f;
    if (s0 > 0.f) m0 -= RESETV;
    if (s1 > 0.f) m1 -= RESETV;

    *reinterpret_cast<float2*>(&out_spike[base]) = make_float2(s0, s1);
    *reinterpret_cast<float2*>(&out_mem[base])   = make_float2(m0, m1);

    float df0 = (s0 > 0.f) ? 0.0f : dfr.x + 1.0f;
    float df1 = (s1 > 0.f) ? 0.0f : dfr.y + 1.0f;
    uint4 u;
    u.x = h2u(__floats2half2_rn(df0, df1));
    u.y = h2u(__floats2half2_rn(__expf(-df0 * INV_TAU), __expf(-df1 * INV_TAU)));
    u.z = h2u(__floats2half2_rn(-__expf(df0 * INV_TAU), -__expf(df1 * INV_TAU)));
    u.w = 0;
    g_Opk[b * (OUT_ / 2) + opi] = u;
}

// ---------------------------------------------------------------------------
// STDP: avg_b [ 1(df>dp) e^{(dp-df)/20} - 1(df<dp) e^{(df-dp)/20} ], half2 math.
// Block tile I=64 x O=64; thread: 2 i (lanes along i -> coalesced epilogue)
// x 8 o (4 half2 pairs). grid (16 o-blk, 16 i-blk) = 256 blocks, 8 warps each.
// ---------------------------------------------------------------------------
__global__ __launch_bounds__(256) void k_stdp(
    const float* __restrict__ W, float* __restrict__ outW)
{
    __shared__ uint4 sI[16][64];   // 16 KB
    __shared__ uint4 sO[16][32];   // 8 KB

    const int tid = threadIdx.x;
    const int tx = tid & 31;       // i-pair lane
    const int ty = tid >> 5;       // o-octet
    const int oBase = blockIdx.x * 64;
    const int iBase = blockIdx.y * 64;
    const int opBase = oBase >> 1;

    float accf[2][4][2];
    #pragma unroll
    for (int j = 0; j < 2; j++)
        #pragma unroll
        for (int c = 0; c < 4; c++) { accf[j][c][0] = 0.f; accf[j][c][1] = 0.f; }

    for (int cb = 0; cb < 8; cb++) {           // 8 chunks of 16 batches
        #pragma unroll
        for (int t = tid; t < 16 * 64; t += 256) {
            int b = t >> 6, i = t & 63;
            sI[b][i] = g_Ipk[(cb * 16 + b) * IN_ + iBase + i];
        }
        #pragma unroll
        for (int t = tid; t < 16 * 32; t += 256) {
            int b = t >> 5, op = t & 31;
            sO[b][op] = g_Opk[(cb * 16 + b) * (OUT_ / 2) + opBase + op];
        }
        __syncthreads();

        __half2 acch[2][4];
        #pragma unroll
        for (int j = 0; j < 2; j++)
            #pragma unroll
            for (int c = 0; c < 4; c++) acch[j][c] = __float2half2_rn(0.f);

        #pragma unroll 4
        for (int b = 0; b < 16; b++) {
            uint4 ov[4], iv[2];
            #pragma unroll
            for (int c = 0; c < 4; c++) ov[c] = sO[b][ty * 4 + c];   // broadcast
            #pragma unroll
            for (int j = 0; j < 2; j++) iv[j] = sI[b][tx * 2 + j];

            #pragma unroll
            for (int j = 0; j < 2; j++) {
                __half2 dp2 = u2h(iv[j].x);
                __half2 p2  = u2h(iv[j].y);
                __half2 q2  = u2h(iv[j].z);
                #pragma unroll
                for (int c = 0; c < 4; c++) {
                    __half2 df2 = u2h(ov[c].x);
                    __half2 gt  = __hgt2(df2, dp2);       // 1.0 / 0.0
                    __half2 lt  = __hlt2(df2, dp2);
                    acch[j][c] = __hfma2(gt, __hmul2(p2, u2h(ov[c].y)), acch[j][c]);
                    acch[j][c] = __hfma2(lt, __hmul2(q2, u2h(ov[c].z)), acch[j][c]);
                }
            }
        }

        #pragma unroll
        for (int j = 0; j < 2; j++)
            #pragma unroll
            for (int c = 0; c < 4; c++) {
                accf[j][c][0] += __low2float(acch[j][c]);
                accf[j][c][1] += __high2float(acch[j][c]);
            }
        __syncthreads();
    }

    // epilogue: newW[o][i0..i0+1], lanes along i -> 256B coalesced per warp
    const int i0 = iBase + tx * 2;
    #pragma unroll
    for (int c = 0; c < 4; c++) {
        #pragma unroll
        for (int h = 0; h < 2; h++) {
            int o = oBase + ty * 8 + c * 2 + h;
            float2 wv = *reinterpret_cast<const float2*>(&W[(size_t)o * IN_ + i0]);
            float2 r  = make_float2(wv.x + accf[0][c][h] * A_SC,
                                    wv.y + accf[1][c][h] * A_SC);
            *reinterpret_cast<float2*>(&outW[(size_t)o * IN_ + i0]) = r;
        }
    }
}

// ---------------------------------------------------------------------------
extern "C" void kernel_launch(void* const* d_in, const int* in_sizes, int n_in,
                              void* d_out, int out_size)
{
    const float* spikes   = (const float*)d_in[0];
    const float* W        = (const float*)d_in[1];
    const float* membrane = (const float*)d_in[2];
    const float* dpre     = (const float*)d_in[3];
    const float* dfire    = (const float*)d_in[4];

    float* out       = (float*)d_out;
    float* out_spike = out;                                   // (B, OUT)
    float* out_W     = out + B_ * OUT_;                       // (OUT, IN)
    float* out_mem   = out + B_ * OUT_ + (size_t)OUT_ * IN_;  // (B, OUT)

    k_transpose<<<dim3(32, 32), dim3(32, 8)>>>(W);
    k_ipack<<<(B_ * IN_) / 256, 256>>>(spikes, dpre);
    k_matmul<<<dim3(32, 4), 256>>>(spikes);
    k_lif<<<(B_ * OUT_ / 2) / 256, 256>>>(membrane, dfire, out_spike, out_mem);
    k_stdp<<<dim3(16, 16), 256>>>(W, out_W);
}